// round 11
// baseline (speedup 1.0000x reference)
#include <cuda_runtime.h>
#include <math.h>
#include <stdint.h>

// Problem constants
#define BATCH 64
#define LDIM  1024
#define FFDIM 8192
#define HDIM  256
#define RDIM  4
#define EPSC  1e-4f

// Scratch
__device__ float    g_mod[BATCH * FFDIM];   // 2 MB, layout [b][f]
__device__ uint32_t g_xa[BATCH * 512];      // x 'a' fp16x2 pairs
__device__ uint32_t g_xc[BATCH * 512];      // x 'c' = fp16(a + (v-a)*32) pairs
__device__ float    g_scale[BATCH * 4];
__device__ float    g_weff[RDIM];
__device__ float    g_beff;
__device__ float    g_magpart[BATCH * 16];

// ---------------------------------------------------------------------------
// fp16 combined-split helpers: v ~= a*(1-1/32) + c/32 in product space
// ---------------------------------------------------------------------------
__device__ __forceinline__ void f16ac(float v, uint16_t& a, uint16_t& c)
{
    uint16_t ah;
    asm("cvt.rn.f16.f32 %0, %1;" : "=h"(ah) : "f"(v));
    float af;
    asm("cvt.f32.f16 %0, %1;" : "=f"(af) : "h"(ah));
    float r = (v - af) * 32.0f;
    uint16_t bh;
    asm("cvt.rn.f16.f32 %0, %1;" : "=h"(bh) : "f"(r));
    float bf;
    asm("cvt.f32.f16 %0, %1;" : "=f"(bf) : "h"(bh));
    asm("cvt.rn.f16.f32 %0, %1;" : "=h"(c) : "f"(af + bf));
    a = ah;
}
__device__ __forceinline__ uint32_t packh(uint16_t a, uint16_t b)
{
    uint32_t w;
    asm("mov.b32 %0, {%1, %2};" : "=r"(w) : "h"(a), "h"(b));
    return w;
}
__device__ __forceinline__ void split4(float4 v, uint32_t& a01, uint32_t& a23,
                                       uint32_t& c01, uint32_t& c23)
{
    uint16_t a0, a1, a2, a3, c0, c1, c2, c3;
    f16ac(v.x, a0, c0);
    f16ac(v.y, a1, c1);
    f16ac(v.z, a2, c2);
    f16ac(v.w, a3, c3);
    a01 = packh(a0, a1); a23 = packh(a2, a3);
    c01 = packh(c0, c1); c23 = packh(c2, c3);
}

__device__ __forceinline__ void mma16(float* d, const uint32_t* a, const uint32_t* b)
{
    asm volatile(
        "mma.sync.aligned.m16n8k16.row.col.f32.f16.f16.f32 "
        "{%0,%1,%2,%3}, {%4,%5,%6,%7}, {%8,%9}, {%0,%1,%2,%3};"
        : "+f"(d[0]), "+f"(d[1]), "+f"(d[2]), "+f"(d[3])
        : "r"(a[0]), "r"(a[1]), "r"(a[2]), "r"(a[3]), "r"(b[0]), "r"(b[1]));
}

// ---------------------------------------------------------------------------
// Kernel 0: pre-split x into packed fp16x2 (a, c). 64 x 256.
// ---------------------------------------------------------------------------
__global__ void __launch_bounds__(256)
k_xsplit(const float* __restrict__ x)
{
    const int idx = blockIdx.x * 256 + threadIdx.x;   // 0..16383 float4s
    float4 v = reinterpret_cast<const float4*>(x)[idx];
    uint32_t a01, a23, c01, c23;
    split4(v, a01, a23, c01, c23);
    reinterpret_cast<uint2*>(g_xa)[idx] = make_uint2(a01, a23);
    reinterpret_cast<uint2*>(g_xc)[idx] = make_uint2(c01, c23);
}

// ---------------------------------------------------------------------------
// Kernel 1: fused GEMM pair + silu via fp16 m16n8k16, 2-MMA combined split.
// D = D_aa*(31/32) + D_cc*(1/32).
// CTA tile M=64 f x N=64 batch, K-tile 32 (2 k16 steps), double buffer.
// smem: packed fp16x2 tiles, row stride 20 words (conflict-free LDS.32).
// 256 threads = 8 warps; warp tile M=16 x N=32.
// ---------------------------------------------------------------------------
#define WSTR   20                    // words per tile row (16 used + 4 pad)
#define TILE_W (64 * WSTR)           // 1280 words per tile
#define ST_WTA 0
#define ST_WTC (1 * TILE_W)
#define ST_WGA (2 * TILE_W)
#define ST_WGC (3 * TILE_W)
#define ST_XA  (4 * TILE_W)
#define ST_XC  (5 * TILE_W)
#define STAGE_WORDS (6 * TILE_W)     // 7680 words = 30720 B
#define GEMM_SMEM_BYTES (2 * STAGE_WORDS * 4)   // 61440 B

__global__ void __launch_bounds__(256, 1)
k_gemm_mma(const float* __restrict__ Wt,
           const float* __restrict__ Wg)
{
    extern __shared__ uint32_t smw[];
    const int t    = threadIdx.x;
    const int warp = t >> 5, lane = t & 31;
    const int gid  = lane >> 2, tig = lane & 3;
    const int mb   = (warp & 3) * 16;     // warp M offset (f)
    const int nb   = (warp >> 2) * 32;    // warp N offset (batch)
    const int f0   = blockIdx.x * 64;

    const float4* Wt4 = reinterpret_cast<const float4*>(Wt);
    const float4* Wg4 = reinterpret_cast<const float4*>(Wg);
    const uint4*  Xa4 = reinterpret_cast<const uint4*>(g_xa);
    const uint4*  Xc4 = reinterpret_cast<const uint4*>(g_xc);

    const int xrow = t >> 2;          // batch row 0..63
    const int xc   = t & 3;           // 4-word group 0..3

    float acc1[2][4][4], acc2[2][4][4];
#pragma unroll
    for (int g = 0; g < 2; g++)
#pragma unroll
        for (int j = 0; j < 4; j++)
#pragma unroll
            for (int c = 0; c < 4; c++) { acc1[g][j][c] = 0.f; acc2[g][j][c] = 0.f; }

    float4 wtp[2], wgp[2];
    uint4  xaq, xcq;
    {
#pragma unroll
        for (int q = 0; q < 2; q++) {
            int idx = q * 256 + t, row = idx >> 3, col = idx & 7;
            wtp[q] = Wt4[(size_t)(f0 + row) * 256 + col];
            wgp[q] = Wg4[(size_t)(f0 + row) * 256 + col];
        }
        xaq = Xa4[xrow * 128 + xc];
        xcq = Xc4[xrow * 128 + xc];
    }

    for (int kt = 0; kt < 32; ++kt) {
        uint32_t* st = smw + (kt & 1) * STAGE_WORDS;
        // split+store W tiles
#pragma unroll
        for (int q = 0; q < 2; q++) {
            int idx = q * 256 + t, row = idx >> 3, col = idx & 7;
            int off = row * WSTR + col * 2;
            uint32_t a01, a23, c01, c23;
            split4(wtp[q], a01, a23, c01, c23);
            *reinterpret_cast<uint2*>(&st[ST_WTA + off]) = make_uint2(a01, a23);
            *reinterpret_cast<uint2*>(&st[ST_WTC + off]) = make_uint2(c01, c23);
            split4(wgp[q], a01, a23, c01, c23);
            *reinterpret_cast<uint2*>(&st[ST_WGA + off]) = make_uint2(a01, a23);
            *reinterpret_cast<uint2*>(&st[ST_WGC + off]) = make_uint2(c01, c23);
        }
        // store x tiles (already split)
        *reinterpret_cast<uint4*>(&st[ST_XA + xrow * WSTR + xc * 4]) = xaq;
        *reinterpret_cast<uint4*>(&st[ST_XC + xrow * WSTR + xc * 4]) = xcq;
        __syncthreads();

        if (kt + 1 < 32) {
            const size_t ko = (size_t)(kt + 1) * 8;   // float4 units
#pragma unroll
            for (int q = 0; q < 2; q++) {
                int idx = q * 256 + t, row = idx >> 3, col = idx & 7;
                wtp[q] = Wt4[(size_t)(f0 + row) * 256 + ko + col];
                wgp[q] = Wg4[(size_t)(f0 + row) * 256 + ko + col];
            }
            xaq = Xa4[xrow * 128 + (kt + 1) * 4 + xc];
            xcq = Xc4[xrow * 128 + (kt + 1) * 4 + xc];
        }

#pragma unroll
        for (int ks = 0; ks < 2; ++ks) {
            const int kb = ks * 8;    // pair offset within tile
            uint32_t Aa[2][4], Ac[2][4], Ba[4][2], Bc[4][2];
#pragma unroll
            for (int g = 0; g < 2; ++g) {
                const uint32_t* ta = st + (g ? ST_WGA : ST_WTA);
                const uint32_t* tc = st + (g ? ST_WGC : ST_WTC);
                int r0 = (mb + gid) * WSTR + kb + tig;
                int r1 = r0 + 8 * WSTR;
                Aa[g][0] = ta[r0];     Aa[g][1] = ta[r1];
                Aa[g][2] = ta[r0 + 4]; Aa[g][3] = ta[r1 + 4];
                Ac[g][0] = tc[r0];     Ac[g][1] = tc[r1];
                Ac[g][2] = tc[r0 + 4]; Ac[g][3] = tc[r1 + 4];
            }
#pragma unroll
            for (int j = 0; j < 4; ++j) {
                int bb = (nb + j * 8 + gid) * WSTR + kb + tig;
                Ba[j][0] = st[ST_XA + bb]; Ba[j][1] = st[ST_XA + bb + 4];
                Bc[j][0] = st[ST_XC + bb]; Bc[j][1] = st[ST_XC + bb + 4];
            }
#pragma unroll
            for (int g = 0; g < 2; ++g)
#pragma unroll
                for (int j = 0; j < 4; ++j) {
                    mma16(acc1[g][j], Aa[g], Ba[j]);
                    mma16(acc2[g][j], Ac[g], Bc[j]);
                }
        }
    }

    // merge: v = D_aa*(31/32) + D_cc*(1/32); silu, transpose, coalesced store
    __syncthreads();
    float* sOut = reinterpret_cast<float*>(smw);   // 64 (b) x 68-stride (f)
#pragma unroll
    for (int j = 0; j < 4; ++j)
#pragma unroll
        for (int c = 0; c < 4; ++c) {
            float tv = fmaf(acc1[0][j][c], 0.96875f, acc2[0][j][c] * 0.03125f);
            float gv = fmaf(acc1[1][j][c], 0.96875f, acc2[1][j][c] * 0.03125f);
            float o  = tv * __fdividef(gv, 1.0f + __expf(-gv));
            int fl = mb + gid + ((c >> 1) << 3);
            int bl = nb + j * 8 + 2 * tig + (c & 1);
            sOut[bl * 68 + fl] = o;
        }
    __syncthreads();

#pragma unroll
    for (int v = 0; v < 4; ++v) {
        int idx = v * 256 + t;
        int row = idx >> 4, q = idx & 15;
        float4 val = *reinterpret_cast<const float4*>(sOut + row * 68 + q * 4);
        *reinterpret_cast<float4*>(&g_mod[(size_t)row * FFDIM + f0 + q * 4]) = val;
    }
}

// ---------------------------------------------------------------------------
// Block reduction helper (256 threads)
// ---------------------------------------------------------------------------
__device__ __forceinline__ float block_reduce_256(float v, float* sh)
{
#pragma unroll
    for (int o = 16; o > 0; o >>= 1) v += __shfl_xor_sync(0xFFFFFFFFu, v, o);
    int w = threadIdx.x >> 5;
    if ((threadIdx.x & 31) == 0) sh[w] = v;
    __syncthreads();
    if (threadIdx.x < 8) {
        v = sh[threadIdx.x];
#pragma unroll
        for (int o = 4; o > 0; o >>= 1) v += __shfl_xor_sync(0x000000FFu, v, o);
    }
    return v;
}

// ---------------------------------------------------------------------------
// Kernel 2: per-(b,k) normalization scales + conv reductions
// ---------------------------------------------------------------------------
__global__ void k_scale(const float* __restrict__ conv_w,
                        const float* __restrict__ conv_b)
{
    __shared__ float sh[8];
    const int g = blockIdx.x;                 // g = b*4 + k
    const float4* p4 = reinterpret_cast<const float4*>(g_mod + (size_t)g * 2048);
    float4 a = p4[threadIdx.x];
    float4 c = p4[threadIdx.x + 256];
    float s = fabsf(a.x) + fabsf(a.y) + fabsf(a.z) + fabsf(a.w)
            + fabsf(c.x) + fabsf(c.y) + fabsf(c.z) + fabsf(c.w);
    s = block_reduce_256(s, sh);
    if (threadIdx.x == 0)
        g_scale[g] = rsqrtf(s * (1.0f / 2048.0f) + EPSC);

    if (g == 0) {
        if (threadIdx.x < RDIM) {
            float w = 0.f;
#pragma unroll
            for (int i = 0; i < RDIM; i++) w += conv_w[i * RDIM + threadIdx.x];
            g_weff[threadIdx.x] = w;
        }
        if (threadIdx.x == RDIM) {
            float b = 0.f;
#pragma unroll
            for (int i = 0; i < RDIM; i++) b += conv_b[i];
            g_beff = b;
        }
    }
}

// ---------------------------------------------------------------------------
// Kernel 3: per-batch magnitude partial sums. (pipelined global loads)
// ---------------------------------------------------------------------------
__global__ void __launch_bounds__(256)
k_mag(const float* __restrict__ ws, const float* __restrict__ wm)
{
    __shared__ float4 wa4[16][2];
    __shared__ float  sh[8];

    const int b  = blockIdx.y;
    const int i0 = blockIdx.x * 16;
    const int t  = threadIdx.x;

    if (t < 128) {
        int k = t >> 6, r = (t >> 4) & 3, il = t & 15;
        reinterpret_cast<float*>(wa4)[il * 8 + k * 4 + r] =
            g_weff[r] * g_scale[b * 4 + k]
            * g_mod[(size_t)b * FFDIM + k * 2048 + r * 512 + (i0 + il)];
    }

    float sb0[4], sb1[4];
    {
        float s0 = g_scale[b * 4 + 0], s1 = g_scale[b * 4 + 1];
#pragma unroll
        for (int r = 0; r < 4; r++) {
            sb0[r] = s0 * g_mod[(size_t)b * FFDIM + 0 * 2048 + r * 512 + HDIM + t];
            sb1[r] = s1 * g_mod[(size_t)b * FFDIM + 1 * 2048 + r * 512 + HDIM + t];
        }
    }
    __syncthreads();

    const float be = g_beff;
    float sum = 0.f;

    float wmc0, wmc1; float2 A1c;
    {
        const int pix = (i0 << 8) + t;
        wmc0 = wm[pix]; wmc1 = wm[65536 + pix];
        A1c  = *reinterpret_cast<const float2*>(&ws[131072 + 2 * pix]);
    }
#pragma unroll
    for (int il = 0; il < 16; il++) {
        float wmn0, wmn1; float2 A1n;
        if (il < 15) {
            const int pixn = ((i0 + il + 1) << 8) + t;
            wmn0 = wm[pixn]; wmn1 = wm[65536 + pixn];
            A1n  = *reinterpret_cast<const float2*>(&ws[131072 + 2 * pixn]);
        }
        float4 w0 = wa4[il][0];
        float4 w1 = wa4[il][1];
        float m0 = be, m1 = be;
        m0 = fmaf(w0.x, sb0[0], m0); m0 = fmaf(w0.y, sb0[1], m0);
        m0 = fmaf(w0.z, sb0[2], m0); m0 = fmaf(w0.w, sb0[3], m0);
        m1 = fmaf(w1.x, sb1[0], m1); m1 = fmaf(w1.y, sb1[1], m1);
        m1 = fmaf(w1.z, sb1[2], m1); m1 = fmaf(w1.w, sb1[3], m1);
        m0 *= wmc0;
        m1 *= wmc1;
        float re = A1c.x * m0 - A1c.y * m1;
        float im = A1c.x * m1 - A1c.y * m0;
        sum += sqrtf(fmaf(re, re, fmaf(im, im, EPSC)));
        wmc0 = wmn0; wmc1 = wmn1; A1c = A1n;
    }
    sum = block_reduce_256(sum, sh);
    if (t == 0) g_magpart[b * 16 + blockIdx.x] = sum;
}

// ---------------------------------------------------------------------------
// Kernel 4: final output. (pipelined global loads)
// ---------------------------------------------------------------------------
__global__ void __launch_bounds__(256)
k_final(const float* __restrict__ ws, const float* __restrict__ wm,
        float* __restrict__ out)
{
    __shared__ float4 wa4[16][4];

    const int b  = blockIdx.y;
    const int i0 = blockIdx.x * 16;
    const int t  = threadIdx.x;

    {
        int k = t >> 6, r = (t >> 4) & 3, il = t & 15;
        reinterpret_cast<float*>(wa4)[il * 16 + k * 4 + r] =
            g_weff[r] * g_scale[b * 4 + k]
            * g_mod[(size_t)b * FFDIM + k * 2048 + r * 512 + (i0 + il)];
    }

    float sbv[4][4];
#pragma unroll
    for (int k = 0; k < 4; k++) {
        float sc = g_scale[b * 4 + k];
#pragma unroll
        for (int r = 0; r < 4; r++)
            sbv[k][r] = sc * g_mod[(size_t)b * FFDIM + k * 2048 + r * 512 + HDIM + t];
    }
    __syncthreads();

    float msum = 0.f;
#pragma unroll
    for (int q = 0; q < 16; q++) msum += g_magpart[b * 16 + q];
    const float inv = rsqrtf(msum * (1.0f / 65536.0f) + EPSC);
    const float be = g_beff;

    float wmc[4]; float2 A0c, A1c;
    {
        const int pix = (i0 << 8) + t;
#pragma unroll
        for (int k = 0; k < 4; k++) wmc[k] = wm[(k << 16) + pix];
        A0c = *reinterpret_cast<const float2*>(&ws[2 * pix]);
        A1c = *reinterpret_cast<const float2*>(&ws[131072 + 2 * pix]);
    }
#pragma unroll
    for (int il = 0; il < 16; il++) {
        float wmn[4]; float2 A0n, A1n;
        if (il < 15) {
            const int pixn = ((i0 + il + 1) << 8) + t;
#pragma unroll
            for (int k = 0; k < 4; k++) wmn[k] = wm[(k << 16) + pixn];
            A0n = *reinterpret_cast<const float2*>(&ws[2 * pixn]);
            A1n = *reinterpret_cast<const float2*>(&ws[131072 + 2 * pixn]);
        }
        const int pix = ((i0 + il) << 8) + t;
        float m[4];
#pragma unroll
        for (int k = 0; k < 4; k++) {
            float4 wk = wa4[il][k];
            float acc = be;
            acc = fmaf(wk.x, sbv[k][0], acc);
            acc = fmaf(wk.y, sbv[k][1], acc);
            acc = fmaf(wk.z, sbv[k][2], acc);
            acc = fmaf(wk.w, sbv[k][3], acc);
            m[k] = wmc[k] * acc;
        }
        float re = A1c.x * m[0] - A1c.y * m[1];
        float im = A1c.x * m[1] - A1c.y * m[0];
        float mwre = fmaf(re, inv, A0c.x);
        float mwim = fmaf(im, inv, A0c.y);
        float den = sqrtf(fmaf(m[2], m[2], fmaf(m[3], m[3], EPSC)));
        out[((size_t)b << 16) + pix] =
            __fdividef(fmaf(mwre, m[2], mwim * m[3]), den);
#pragma unroll
        for (int k = 0; k < 4; k++) wmc[k] = wmn[k];
        A0c = A0n; A1c = A1n;
    }
}

// ---------------------------------------------------------------------------
// Launch
// ---------------------------------------------------------------------------
extern "C" void kernel_launch(void* const* d_in, const int* in_sizes, int n_in,
                              void* d_out, int out_size)
{
    const float* x      = (const float*)d_in[0];
    const float* Wt     = (const float*)d_in[1];
    const float* Wg     = (const float*)d_in[2];
    const float* ws     = (const float*)d_in[3];
    const float* wm     = (const float*)d_in[4];
    const float* conv_w = (const float*)d_in[5];
    const float* conv_b = (const float*)d_in[6];
    float* out = (float*)d_out;

    cudaFuncSetAttribute(k_gemm_mma,
                         cudaFuncAttributeMaxDynamicSharedMemorySize,
                         GEMM_SMEM_BYTES);

    k_xsplit<<<64, 256>>>(x);
    k_gemm_mma<<<FFDIM / 64, 256, GEMM_SMEM_BYTES>>>(Wt, Wg);
    k_scale<<<BATCH * 4, 256>>>(conv_w, conv_b);
    k_mag<<<dim3(16, BATCH), 256>>>(ws, wm);
    k_final<<<dim3(16, BATCH), 256>>>(ws, wm, out);
}